// round 12
// baseline (speedup 1.0000x reference)
#include <cuda_runtime.h>
#include <cstdint>

#define TPB 128

namespace {
constexpr int Cn = 64, Hn = 112, Wn = 112, Fn = 128;
constexpr int PIX   = Hn * Wn;           // 12544
constexpr int CPW   = 484;               // s_in words per channel (4 rows x 120 + pad)
constexpr int ROWW  = 120;               // padded row width (words)
constexpr int SIN_W = 32 * CPW;          // 15488 words
constexpr int BPK   = 5120;              // packed-B words per (tap, c-half): 4s*2wn*32lane*20
constexpr int SMEM_WORDS = SIN_W + 2 * BPK;  // 25728
constexpr int SMEM_BYTES = SMEM_WORDS * 4;   // 102912
}

// fragment-packed tf32 weights: [tap][half][s][wnIdx][lane][20] (16 used + 4 pad)
__device__ __align__(16) uint32_t g_wt[9 * 2 * BPK];

__device__ __forceinline__ uint32_t f2tf32(float x) {
    uint32_t r;
    asm("cvt.rna.tf32.f32 %0, %1;" : "=r"(r) : "f"(x));
    return r;
}
__device__ __forceinline__ uint32_t smem_u32(const void* p) {
    uint32_t a;
    asm("{ .reg .u64 t; cvta.to.shared.u64 t, %1; cvt.u32.u64 %0, t; }" : "=r"(a) : "l"(p));
    return a;
}
__device__ __forceinline__ void cpa16z(uint32_t dst, const void* src, int sz) {
    asm volatile("cp.async.cg.shared.global [%0], [%1], 16, %2;"
                 :: "r"(dst), "l"(src), "r"(sz));
}
__device__ __forceinline__ void cpa16(uint32_t dst, const void* src) {
    asm volatile("cp.async.cg.shared.global [%0], [%1], 16;"
                 :: "r"(dst), "l"(src));
}
#define CP_COMMIT() asm volatile("cp.async.commit_group;" ::: "memory")
#define CP_WAIT0()  asm volatile("cp.async.wait_group 0;"  ::: "memory")

// build fragment-packed B: word i -> (tap, half, s, wnIdx, lane, w)
__global__ void pack_wt_kernel(const float* __restrict__ wt) {
    int i = blockIdx.x * 256 + threadIdx.x;
    if (i >= 9 * 2 * BPK) return;
    int w     = i % 20;
    int j     = i / 20;
    int lane  = j % 32;
    int t     = j / 32;
    int wnIdx = t % 2;
    int t2    = t / 2;
    int s     = t2 % 4;
    int t3    = t2 / 4;
    int half  = t3 % 2;
    int tap   = t3 / 2;
    uint32_t val = 0;
    if (w < 16) {
        int kk = w & 1;
        int ni = w >> 1;
        int c  = half * 32 + s * 8 + (lane & 3) + kk * 4;
        int f  = wnIdx * 64 + ni * 8 + (lane >> 2);
        val = f2tf32(wt[f * 576 + c * 9 + tap]);
    }
    g_wt[i] = val;
}

// D[m=128 pixels][n=128 filters]; 4 warps, warp tile 64x64; explicit
// double-buffered register fragments so LDS of step s+1 hides under MMAs of s.
__global__ void __launch_bounds__(TPB, 2)
conv_mma8_kernel(const float* __restrict__ in, float* __restrict__ out)
{
    extern __shared__ uint32_t smem[];
    const uint32_t sbase = smem_u32(smem);

    const int tid  = threadIdx.x;
    const int lane = tid & 31;
    const int wid  = tid >> 5;          // 0..3
    const int wnIdx = wid >> 1;         // 0 or 1
    const int bb   = blockIdx.y;
    const int p0   = blockIdx.x * 128;
    const int py0  = p0 / Wn;
    const int px0  = p0 - py0 * Wn;     // multiple of 16, <= 96

    const int wm0 = (wid & 1) * 64;
    const float* in_b = in + (size_t)bb * Cn * PIX;

    // per-thread A fragment offsets: 8 m-values -> word offset (r*120 + x + 3)
    int om[8];
#pragma unroll
    for (int q = 0; q < 8; ++q) {
        int m = wm0 + (lane >> 2) + (q >> 1) * 16 + (q & 1) * 8;
        int x = px0 + m;
        int r = 0;
        if (x >= Wn) { x -= Wn; r = 1; }
        om[q] = r * ROWW + x + 3;
    }

    // zero the x-borders (cols 3 and 116) once; never overwritten by copies
#pragma unroll
    for (int j = 0; j < 2; ++j) {
        int e = j * TPB + tid;            // 0..255
        int c = e >> 3, ry = (e >> 1) & 3, side = e & 1;
        smem[c * CPW + ry * ROWW + (side ? 116 : 3)] = 0;
    }

    float acc[4][8][4];
#pragma unroll
    for (int mi = 0; mi < 4; ++mi)
#pragma unroll
        for (int ni = 0; ni < 8; ++ni)
#pragma unroll
            for (int c = 0; c < 4; ++c) acc[mi][ni][c] = 0.f;

    auto stage_sin = [&](int c0) {
#pragma unroll
        for (int i = 0; i < 28; ++i) {          // 3584 cpa16 / 128 threads
            int e   = i * TPB + tid;
            int x16 = e % 28;
            int cr  = e / 28;                    // 0..127
            int ry  = cr & 3;
            int c   = cr >> 2;
            int y   = py0 - 1 + ry;
            int yc  = min(max(y, 0), Hn - 1);
            const float* src = in_b + (size_t)(c0 + c) * PIX + yc * Wn + x16 * 4;
            int sz = ((unsigned)y < (unsigned)Hn) ? 16 : 0;
            cpa16z(sbase + (c * CPW + ry * ROWW + 4 + x16 * 4) * 4, src, sz);
        }
    };
    auto stage_B = [&](int tap, int half, int buf) {
        const uint32_t* wb = g_wt + (size_t)(tap * 2 + half) * BPK;
#pragma unroll
        for (int i = 0; i < 10; ++i) {           // 1280 cpa16 / 128 threads
            int e = i * TPB + tid;
            cpa16(sbase + (SIN_W + buf * BPK + e * 4) * 4, wb + e * 4);
        }
    };
    auto loadA = [&](int dyx, int s, uint32_t af[4][4]) {
        const int cb = s * 8 + (lane & 3);
        const uint32_t* pa  = smem + cb * CPW + dyx;
        const uint32_t* pa4 = pa + 4 * CPW;
#pragma unroll
        for (int mi = 0; mi < 4; ++mi) {
            af[mi][0] = pa [om[2 * mi]];
            af[mi][1] = pa [om[2 * mi + 1]];
            af[mi][2] = pa4[om[2 * mi]];
            af[mi][3] = pa4[om[2 * mi + 1]];
        }
    };
    auto loadB = [&](const uint32_t* sB, int s, uint4 bbf[4]) {
        const uint32_t* pb = sB + ((s * 2 + wnIdx) * 32 + lane) * 20;
        bbf[0] = *(const uint4*)(pb + 0);
        bbf[1] = *(const uint4*)(pb + 4);
        bbf[2] = *(const uint4*)(pb + 8);
        bbf[3] = *(const uint4*)(pb + 12);
    };

    uint32_t af2[2][4][4];
    uint4    bb4[2][4];

#pragma unroll 1
    for (int half = 0; half < 2; ++half) {
        const int c0 = half * 32;
        __syncthreads();                  // prior readers of s_in done
        stage_sin(c0);
        stage_B(0, half, 0);
        CP_COMMIT();
        CP_WAIT0();
        __syncthreads();                  // s_in + B[0] visible
        stage_B(1, half, 1);              // overlaps tap 0 compute
        CP_COMMIT();

#pragma unroll 1
        for (int tap = 0; tap < 9; ++tap) {
            const int dy = tap / 3, dx = tap - dy * 3;
            const int dyx = dy * ROWW + dx;
            const uint32_t* sB = smem + SIN_W + (tap & 1) * BPK;

            loadA(dyx, 0, af2[0]);
            loadB(sB, 0, bb4[0]);
#pragma unroll
            for (int s = 0; s < 4; ++s) {
                if (s < 3) {              // prefetch next step under this step's MMAs
                    loadA(dyx, s + 1, af2[(s + 1) & 1]);
                    loadB(sB, s + 1, bb4[(s + 1) & 1]);
                }
                const uint32_t (*af)[4] = af2[s & 1];
                const uint4* cur = bb4[s & 1];
                const uint32_t barr[16] = {
                    cur[0].x, cur[0].y, cur[0].z, cur[0].w,
                    cur[1].x, cur[1].y, cur[1].z, cur[1].w,
                    cur[2].x, cur[2].y, cur[2].z, cur[2].w,
                    cur[3].x, cur[3].y, cur[3].z, cur[3].w };
#pragma unroll
                for (int mi = 0; mi < 4; ++mi)
#pragma unroll
                    for (int ni = 0; ni < 8; ++ni)
                        asm volatile(
                            "mma.sync.aligned.m16n8k8.row.col.f32.tf32.tf32.f32 "
                            "{%0,%1,%2,%3}, {%4,%5,%6,%7}, {%8,%9}, {%0,%1,%2,%3};"
                            : "+f"(acc[mi][ni][0]), "+f"(acc[mi][ni][1]),
                              "+f"(acc[mi][ni][2]), "+f"(acc[mi][ni][3])
                            : "r"(af[mi][0]), "r"(af[mi][1]),
                              "r"(af[mi][2]), "r"(af[mi][3]),
                              "r"(barr[2 * ni]), "r"(barr[2 * ni + 1]));
            }

            if (tap < 8) {
                CP_WAIT0();               // B[tap+1] landed
                __syncthreads();          // all warps done reading buf[tap&1]
                if (tap < 7) {            // refill the buffer just freed
                    stage_B(tap + 2, half, tap & 1);
                    CP_COMMIT();
                }
            }
        }
    }

    // ---- coalesced epilogue: acc -> smem transpose -> 128B-contiguous STG ----
    float* sf = (float*)smem;            // s_out[m][n'] pitch 68 (reuses s_in)
    float* out_b = out + (size_t)bb * Fn * PIX + p0;
#pragma unroll 1
    for (int pass = 0; pass < 2; ++pass) {
        __syncthreads();                 // smem free / previous pass consumed
        if (wnIdx == pass) {
#pragma unroll
            for (int mi = 0; mi < 4; ++mi) {
                int r0 = wm0 + mi * 16 + (lane >> 2);
#pragma unroll
                for (int ni = 0; ni < 8; ++ni) {
                    int nn = ni * 8 + (lane & 3) * 2;
                    *(float2*)&sf[r0 * 68 + nn] =
                        make_float2(acc[mi][ni][0], acc[mi][ni][1]);
                    *(float2*)&sf[(r0 + 8) * 68 + nn] =
                        make_float2(acc[mi][ni][2], acc[mi][ni][3]);
                }
            }
        }
        __syncthreads();
        // thread tid owns pixel m=tid; 16x LDS.128 (conflict-free), 64 coalesced STG
#pragma unroll
        for (int jj = 0; jj < 16; ++jj) {
            float4 v = *(const float4*)&sf[tid * 68 + jj * 4];
            float* dst = out_b + (size_t)(pass * 64 + jj * 4) * PIX + tid;
            dst[0]               = v.x;
            dst[(size_t)PIX]     = v.y;
            dst[(size_t)2 * PIX] = v.z;
            dst[(size_t)3 * PIX] = v.w;
        }
    }
}

extern "C" void kernel_launch(void* const* d_in, const int* in_sizes, int n_in,
                              void* d_out, int out_size)
{
    (void)in_sizes; (void)n_in; (void)out_size;
    const float* in = (const float*)d_in[0];   // [32,64,112,112]
    const float* wt = (const float*)d_in[1];   // [128,64,3,3]
    float* out = (float*)d_out;                // [32,128,112,112]

    static bool attr_set = false;
    if (!attr_set) {
        cudaFuncSetAttribute(conv_mma8_kernel,
                             cudaFuncAttributeMaxDynamicSharedMemorySize, SMEM_BYTES);
        attr_set = true;
    }
    pack_wt_kernel<<<(9 * 2 * BPK + 255) / 256, 256>>>(wt);
    dim3 grid(PIX / 128, 32);                  // (98, 32)
    conv_mma8_kernel<<<grid, TPB, SMEM_BYTES>>>(in, out);
}

// round 13
// speedup vs baseline: 1.6744x; 1.6744x over previous
#include <cuda_runtime.h>
#include <cuda_fp16.h>
#include <cstdint>

#define TPB 128

namespace {
constexpr int Cn = 64, Hn = 112, Wn = 112, Fn = 128;
constexpr int PIX   = Hn * Wn;           // 12544
constexpr int CPW   = 484;               // words per channel-pair (4 rows x 120 + pad)
constexpr int ROWW  = 120;               // padded row width (words; 1 word = half2)
constexpr int SINH_W = 32 * CPW;         // 15488 words (32 channel pairs)
constexpr int BPT   = 5120;              // packed-B words per tap: 4s*2wn*32lane*20
constexpr int SMEM_WORDS = SINH_W + 2 * BPT; // 25728
constexpr int SMEM_BYTES = SMEM_WORDS * 4;   // 102912
}

// fragment-packed fp16 weights: [tap][s(4)][wnIdx(2)][lane(32)][20] (16 used + 4 pad)
__device__ __align__(16) uint32_t g_wt[9 * BPT];

__device__ __forceinline__ uint32_t smem_u32(const void* p) {
    uint32_t a;
    asm("{ .reg .u64 t; cvta.to.shared.u64 t, %1; cvt.u32.u64 %0, t; }" : "=r"(a) : "l"(p));
    return a;
}
__device__ __forceinline__ void cpa16(uint32_t dst, const void* src) {
    asm volatile("cp.async.cg.shared.global [%0], [%1], 16;"
                 :: "r"(dst), "l"(src));
}
#define CP_COMMIT() asm volatile("cp.async.commit_group;" ::: "memory")
#define CP_WAIT0()  asm volatile("cp.async.wait_group 0;"  ::: "memory")

// build fp16 fragment-packed B for m16n8k16
__global__ void pack_wt_h_kernel(const float* __restrict__ wt) {
    int i = blockIdx.x * 256 + threadIdx.x;
    if (i >= 9 * BPT) return;
    int w     = i % 20;
    int j     = i / 20;
    int lane  = j % 32;
    int t     = j / 32;
    int wnIdx = t % 2;
    int t2    = t / 2;
    int s     = t2 % 4;
    int tap   = t2 / 4;
    uint32_t val = 0;
    if (w < 16) {
        int ni    = w >> 1;
        int which = w & 1;                  // 0 -> b0 (k 0..7), 1 -> b1 (k 8..15)
        int l3    = lane & 3;
        int f  = wnIdx * 64 + ni * 8 + (lane >> 2);
        int c0 = s * 16 + which * 8 + 2 * l3;   // even k
        float v0 = wt[f * 576 + c0 * 9 + tap];
        float v1 = wt[f * 576 + (c0 + 1) * 9 + tap];
        __half2 h = __floats2half2_rn(v0, v1);  // low = even k
        val = *(uint32_t*)&h;
    }
    g_wt[i] = val;
}

// D[m=128 pixels][n=128 filters]; 4 warps, warp tile 64x64; fp16 m16n8k16 MMA
__global__ void __launch_bounds__(TPB, 2)
conv_hmma_kernel(const float* __restrict__ in, float* __restrict__ out)
{
    extern __shared__ uint32_t smem[];
    const uint32_t sbase = smem_u32(smem);

    const int tid  = threadIdx.x;
    const int lane = tid & 31;
    const int wid  = tid >> 5;          // 0..3
    const int wnIdx = wid >> 1;         // 0 or 1
    const int bb   = blockIdx.y;
    const int p0   = blockIdx.x * 128;
    const int py0  = p0 / Wn;
    const int px0  = p0 - py0 * Wn;     // multiple of 16, <= 96

    const int wm0 = (wid & 1) * 64;
    const float* in_b = in + (size_t)bb * Cn * PIX;

    // per-thread A fragment offsets: 8 m-values -> word offset (r*120 + x + 3)
    int om[8];
#pragma unroll
    for (int q = 0; q < 8; ++q) {
        int m = wm0 + (lane >> 2) + (q >> 1) * 16 + (q & 1) * 8;
        int x = px0 + m;
        int r = 0;
        if (x >= Wn) { x -= Wn; r = 1; }
        om[q] = r * ROWW + x + 3;
    }

    // zero the x-border words (cols 3 and 116); never overwritten by staging
#pragma unroll
    for (int j = 0; j < 2; ++j) {
        int e = j * TPB + tid;            // 0..255
        int cp = e >> 3, ry = (e >> 1) & 3, side = e & 1;
        smem[cp * CPW + ry * ROWW + (side ? 116 : 3)] = 0;
    }

    float acc[4][8][4];
#pragma unroll
    for (int mi = 0; mi < 4; ++mi)
#pragma unroll
        for (int ni = 0; ni < 8; ++ni)
#pragma unroll
            for (int c = 0; c < 4; ++c) acc[mi][ni][c] = 0.f;

    // ---- stage input once: all 64 channels as half2 channel pairs ----
    // unit e: (cp, ry, x-block of 4); LDG 2x float4 -> 4x half2 -> STS.128
    {
#pragma unroll
        for (int i = 0; i < 28; ++i) {      // 3584 units / 128 threads
            int e   = i * TPB + tid;
            int x4  = e % 28;
            int t   = e / 28;
            int ry  = t & 3;
            int cp  = t >> 2;               // 0..31
            int y   = py0 - 1 + ry;
            float4 fa, fb;
            if ((unsigned)y < (unsigned)Hn) {
                const float* base = in_b + (size_t)(2 * cp) * PIX + y * Wn + x4 * 4;
                fa = *(const float4*)base;
                fb = *(const float4*)(base + PIX);
            } else {
                fa = make_float4(0.f, 0.f, 0.f, 0.f);
                fb = fa;
            }
            __half2 h0 = __floats2half2_rn(fa.x, fb.x);
            __half2 h1 = __floats2half2_rn(fa.y, fb.y);
            __half2 h2 = __floats2half2_rn(fa.z, fb.z);
            __half2 h3 = __floats2half2_rn(fa.w, fb.w);
            uint4 v = make_uint4(*(uint32_t*)&h0, *(uint32_t*)&h1,
                                 *(uint32_t*)&h2, *(uint32_t*)&h3);
            *(uint4*)&smem[cp * CPW + ry * ROWW + 4 + x4 * 4] = v;
        }
    }

    auto stage_B = [&](int tap, int buf) {
        const uint32_t* wb = g_wt + (size_t)tap * BPT;
#pragma unroll
        for (int i = 0; i < 10; ++i) {       // 1280 cpa16 / 128 threads
            int e = i * TPB + tid;
            cpa16(sbase + (SINH_W + buf * BPT + e * 4) * 4, wb + e * 4);
        }
    };

    stage_B(0, 0);
    CP_COMMIT();
    CP_WAIT0();
    __syncthreads();                  // s_in (STS) + B[0] visible to all
    stage_B(1, 1);                    // overlaps tap 0 compute
    CP_COMMIT();

    // NOTE: wait half2 packs (even-ch, odd-ch) per pixel; A fragment k pairs map
    // to channel pairs cp = 8s + (lane&3) (k 0..7) and +4 (k 8..15).
#pragma unroll 1
    for (int tap = 0; tap < 9; ++tap) {
        const int dy = tap / 3, dx = tap - dy * 3;
        const int dyx = dy * ROWW + dx;
        const uint32_t* sB = smem + SINH_W + (tap & 1) * BPT;

        // 4 k-steps of K=16 covering all 64 channels
#pragma unroll
        for (int s = 0; s < 4; ++s) {
            const uint32_t* pa  = smem + (s * 8 + (lane & 3)) * CPW + dyx;
            const uint32_t* pa4 = pa + 4 * CPW;
            uint32_t af[4][4];
#pragma unroll
            for (int mi = 0; mi < 4; ++mi) {
                af[mi][0] = pa [om[2 * mi]];
                af[mi][1] = pa [om[2 * mi + 1]];
                af[mi][2] = pa4[om[2 * mi]];
                af[mi][3] = pa4[om[2 * mi + 1]];
            }
            // packed B fragment: 4x LDS.128, conflict-free (20-word stride)
            const uint32_t* pb = sB + ((s * 2 + wnIdx) * 32 + lane) * 20;
            uint4 b0 = *(const uint4*)(pb + 0);
            uint4 b1 = *(const uint4*)(pb + 4);
            uint4 b2 = *(const uint4*)(pb + 8);
            uint4 b3 = *(const uint4*)(pb + 12);
            const uint32_t barr[16] = {
                b0.x, b0.y, b0.z, b0.w, b1.x, b1.y, b1.z, b1.w,
                b2.x, b2.y, b2.z, b2.w, b3.x, b3.y, b3.z, b3.w };
#pragma unroll
            for (int mi = 0; mi < 4; ++mi)
#pragma unroll
                for (int ni = 0; ni < 8; ++ni)
                    asm volatile(
                        "mma.sync.aligned.m16n8k16.row.col.f32.f16.f16.f32 "
                        "{%0,%1,%2,%3}, {%4,%5,%6,%7}, {%8,%9}, {%0,%1,%2,%3};"
                        : "+f"(acc[mi][ni][0]), "+f"(acc[mi][ni][1]),
                          "+f"(acc[mi][ni][2]), "+f"(acc[mi][ni][3])
                        : "r"(af[mi][0]), "r"(af[mi][1]),
                          "r"(af[mi][2]), "r"(af[mi][3]),
                          "r"(barr[2 * ni]), "r"(barr[2 * ni + 1]));
        }

        if (tap < 8) {
            CP_WAIT0();               // B[tap+1] landed
            __syncthreads();          // all warps done reading buf[tap&1]
            if (tap < 7) {            // refill the buffer just freed
                stage_B(tap + 2, tap & 1);
                CP_COMMIT();
            }
        }
    }

    // ---- coalesced epilogue: acc -> smem transpose -> 128B-contiguous STG ----
    float* sf = (float*)smem;            // s_out[m][n'] pitch 68 (reuses s_in)
    float* out_b = out + (size_t)bb * Fn * PIX + p0;
#pragma unroll 1
    for (int pass = 0; pass < 2; ++pass) {
        __syncthreads();                 // smem free / previous pass consumed
        if (wnIdx == pass) {
#pragma unroll
            for (int mi = 0; mi < 4; ++mi) {
                int r0 = wm0 + mi * 16 + (lane >> 2);
#pragma unroll
                for (int ni = 0; ni < 8; ++ni) {
                    int nn = ni * 8 + (lane & 3) * 2;
                    *(float2*)&sf[r0 * 68 + nn] =
                        make_float2(acc[mi][ni][0], acc[mi][ni][1]);
                    *(float2*)&sf[(r0 + 8) * 68 + nn] =
                        make_float2(acc[mi][ni][2], acc[mi][ni][3]);
                }
            }
        }
        __syncthreads();
        // thread tid owns pixel m=tid; 16x LDS.128 (conflict-free), 64 coalesced STG
#pragma unroll
        for (int jj = 0; jj < 16; ++jj) {
            float4 v = *(const float4*)&sf[tid * 68 + jj * 4];
            float* dst = out_b + (size_t)(pass * 64 + jj * 4) * PIX + tid;
            dst[0]               = v.x;
            dst[(size_t)PIX]     = v.y;
            dst[(size_t)2 * PIX] = v.z;
            dst[(size_t)3 * PIX] = v.w;
        }
    }
}

extern "C" void kernel_launch(void* const* d_in, const int* in_sizes, int n_in,
                              void* d_out, int out_size)
{
    (void)in_sizes; (void)n_in; (void)out_size;
    const float* in = (const float*)d_in[0];   // [32,64,112,112]
    const float* wt = (const float*)d_in[1];   // [128,64,3,3]
    float* out = (float*)d_out;                // [32,128,112,112]

    static bool attr_set = false;
    if (!attr_set) {
        cudaFuncSetAttribute(conv_hmma_kernel,
                             cudaFuncAttributeMaxDynamicSharedMemorySize, SMEM_BYTES);
        attr_set = true;
    }
    pack_wt_h_kernel<<<(9 * BPT + 255) / 256, 256>>>(wt);
    dim3 grid(PIX / 128, 32);                  // (98, 32)
    conv_hmma_kernel<<<grid, TPB, SMEM_BYTES>>>(in, out);
}